// round 15
// baseline (speedup 1.0000x reference)
#include <cuda_runtime.h>
#include <math.h>
#include <stdint.h>

#define NN 100000
#define EE 1600000
#define GG 64

// ---------------- scratch (device globals; no allocation allowed) ----------
__device__ uint32_t g_hb[NN * 64];      // bf16x2 h (the ONLY h tensor)
__device__ uint32_t g_zb[NN * 128];     // bf16x2 z (MLP hidden, pre-BN)
__device__ uint32_t g_aggb[NN * 64];    // bf16x2 agg = (1+eps)h + sum h[src]
__device__ double   g_sum[256];
__device__ double   g_sumsq[256];
__device__ float    g_pool[2 * GG * 128];
__device__ float    g_cnt[2 * GG];
__device__ float    g_fc1o[GG * 256];
__device__ float    g_fc2o[GG * 64];
// preconverted weights, [n][k] bf16 (uint16), refreshed per branch
__device__ uint16_t g_eB[128 * 1024];          // embW: n=128, k=1024
__device__ uint16_t g_w1B[4 * 256 * 128];      // W1[i]: n=256, k=128
__device__ uint16_t g_w2B[4 * 128 * 256];      // W2[i]: n=128, k=256

// ---------------- helpers ---------------------------------------------------
__device__ __forceinline__ uint32_t cvt2(float e0, float e1) {
    uint32_t p;
    asm("cvt.rn.bf16x2.f32 %0, %1, %2;" : "=r"(p) : "f"(e1), "f"(e0));
    return p;
}
__device__ __forceinline__ float bflo(uint32_t u) { return __uint_as_float(u << 16); }
__device__ __forceinline__ float bfhi(uint32_t u) { return __uint_as_float(u & 0xFFFF0000u); }

__device__ __forceinline__ void mma16816(float* c, const uint32_t* a, const uint32_t* b) {
    asm volatile("mma.sync.aligned.m16n8k16.row.col.f32.bf16.bf16.f32 "
                 "{%0,%1,%2,%3}, {%4,%5,%6,%7}, {%8,%9}, {%0,%1,%2,%3};"
                 : "+f"(c[0]), "+f"(c[1]), "+f"(c[2]), "+f"(c[3])
                 : "r"(a[0]), "r"(a[1]), "r"(a[2]), "r"(a[3]), "r"(b[0]), "r"(b[1]));
}

// ---------------- weight pre-conversion ------------------------------------
// src W is [K][Nn] fp32 (layer = blockIdx.y); dst H is [Nn][K] bf16
__global__ void convB_kernel(const float* __restrict__ W, uint16_t* __restrict__ H,
                             int K, int Nn) {
    const float* src = W + (size_t)blockIdx.y * K * Nn;
    uint32_t* dh = reinterpret_cast<uint32_t*>(H) + (size_t)blockIdx.y * (K * Nn / 2);
    int idx = blockIdx.x * 256 + threadIdx.x;          // over (K/2)*Nn
    if (idx >= (K / 2) * Nn) return;
    int k2 = idx / Nn, n = idx - k2 * Nn;
    float e0 = __ldg(&src[(size_t)(2 * k2) * Nn + n]);
    float e1 = __ldg(&src[(size_t)(2 * k2 + 1) * Nn + n]);
    dh[(size_t)n * (K / 2) + k2] = cvt2(e0, e1);
}

// ---------------- bf16 mma.sync GEMM (proven loop, fused agg-init) ----------
// MODE 0: hb = bf16(Aext @ B + bias);  aggb = bf16((1+eps0)*hb)
// MODE 1: zb = bf16(aggb @ B + bias)   (grid.y=2; BN stats fp32)
// MODE 2: hb = bf16(relu(relu(BN(zb)) @ B + bias + hb));  aggb = bf16((1+epsN)*hb)
//          (BN scale/shift computed per-CTA from g_sum/g_sumsq)
#define AS 40   // smem row stride in bf16 elems (80 B)

template <int MODE>
__global__ __launch_bounds__(256, 2)
void mma_gemm(const float* __restrict__ Aext, const uint16_t* __restrict__ BH,
              const float* __restrict__ bias,
              const float* __restrict__ gam, const float* __restrict__ bet,
              const float* __restrict__ epsn)
{
    constexpr int K   = (MODE == 0) ? 1024 : ((MODE == 1) ? 128 : 256);
    constexpr int NCHUNK = K / 32;

    __shared__ __align__(16) uint16_t Ahi[128 * AS];
    __shared__ __align__(16) uint16_t Bhi[128 * AS];
    __shared__ float s_sum[128], s_sumsq[128];
    __shared__ float s_scale[256], s_shift[256];

    const int tid  = threadIdx.x;
    const int lane = tid & 31, wid = tid >> 5;
    const int bm = blockIdx.x * 128;
    const int bn = blockIdx.y * 128;
    const int wm = (wid >> 1) * 32;
    const int wn = (wid & 1) * 64;
    const int grp = lane >> 2, qid = lane & 3;

    if (MODE == 1 && tid < 128) { s_sum[tid] = 0.f; s_sumsq[tid] = 0.f; }
    if (MODE == 2) {   // fused bn_finalize: every CTA computes scale/shift
        float mean = (float)(g_sum[tid] / (double)NN);
        float var  = (float)(g_sumsq[tid] / (double)NN) - mean * mean;
        float sc = __ldg(&gam[tid]) * rsqrtf(var + 1e-5f);
        s_scale[tid] = sc;
        s_shift[tid] = fmaf(-mean, sc, __ldg(&bet[tid]));
        __syncthreads();
    }

    float acc[2][8][4];
#pragma unroll
    for (int mt = 0; mt < 2; mt++)
#pragma unroll
        for (int nt = 0; nt < 8; nt++)
#pragma unroll
            for (int q = 0; q < 4; q++) acc[mt][nt][q] = 0.f;

    const int arow = tid >> 1, ahalf = tid & 1;        // A loader: row, 16-col half
    const int bnid = tid & 127, bkh = (tid >> 7) * 16; // B loader: n col, 16-k half
    const int rA = bm + arow;

    auto loadA = [&](int k0, float* v) {
        if (rA < NN) {
            if (MODE == 2) {             // bf16 z read + BN + ReLU
                const uint32_t* zp = g_zb + ((size_t)rA * 256 + k0 + ahalf * 16) / 2;
                uint32_t u[8];
                *reinterpret_cast<uint4*>(u)     = __ldg(reinterpret_cast<const uint4*>(zp));
                *reinterpret_cast<uint4*>(u + 4) = __ldg(reinterpret_cast<const uint4*>(zp + 4));
                const int kb = k0 + ahalf * 16;
#pragma unroll
                for (int j = 0; j < 8; j++) {
                    v[2 * j + 0] = fmaxf(fmaf(bflo(u[j]), s_scale[kb + 2 * j],     s_shift[kb + 2 * j]), 0.f);
                    v[2 * j + 1] = fmaxf(fmaf(bfhi(u[j]), s_scale[kb + 2 * j + 1], s_shift[kb + 2 * j + 1]), 0.f);
                }
            } else if (MODE == 1) {      // bf16 agg read
                const uint32_t* ap = g_aggb + ((size_t)rA * 128 + k0 + ahalf * 16) / 2;
                uint32_t u[8];
                *reinterpret_cast<uint4*>(u)     = __ldg(reinterpret_cast<const uint4*>(ap));
                *reinterpret_cast<uint4*>(u + 4) = __ldg(reinterpret_cast<const uint4*>(ap + 4));
#pragma unroll
                for (int j = 0; j < 8; j++) {
                    v[2 * j + 0] = bflo(u[j]);
                    v[2 * j + 1] = bfhi(u[j]);
                }
            } else {                     // fp32 x read (MODE0)
                const float* ap = Aext + (size_t)rA * K + k0 + ahalf * 16;
#pragma unroll
                for (int q = 0; q < 4; q++)
                    *reinterpret_cast<float4*>(v + 4 * q) =
                        __ldg(reinterpret_cast<const float4*>(ap + 4 * q));
            }
        } else {
#pragma unroll
            for (int j = 0; j < 16; j++) v[j] = 0.f;
        }
    };
    auto loadB = [&](int k0, uint32_t* vb) {   // 16 bf16 = 8 uint32, preconverted
        const uint32_t* ph = reinterpret_cast<const uint32_t*>(BH) +
                             ((size_t)(bn + bnid) * K + k0 + bkh) / 2;
        *reinterpret_cast<uint4*>(vb)     = __ldg(reinterpret_cast<const uint4*>(ph));
        *reinterpret_cast<uint4*>(vb + 4) = __ldg(reinterpret_cast<const uint4*>(ph + 4));
    };
    auto storeA = [&](const float* v) {
#pragma unroll
        for (int q = 0; q < 2; q++) {
            uint32_t hs[4];
#pragma unroll
            for (int p = 0; p < 4; p++)
                hs[p] = cvt2(v[q * 8 + p * 2], v[q * 8 + p * 2 + 1]);
            const int c = ahalf * 16 + q * 8;
            *reinterpret_cast<uint4*>(&Ahi[arow * AS + c]) = make_uint4(hs[0], hs[1], hs[2], hs[3]);
        }
    };
    auto storeB = [&](const uint32_t* vb) {
        *reinterpret_cast<uint4*>(&Bhi[bnid * AS + bkh])     = *reinterpret_cast<const uint4*>(vb);
        *reinterpret_cast<uint4*>(&Bhi[bnid * AS + bkh + 8]) = *reinterpret_cast<const uint4*>(vb + 4);
    };
    auto mmaStep = [&]() {
#pragma unroll
        for (int s = 0; s < 32; s += 16) {
            uint32_t ah[2][4];
#pragma unroll
            for (int mt = 0; mt < 2; mt++) {
                const int r0 = (wm + mt * 16 + grp) * AS + s + qid * 2;
                const int r8 = r0 + 8 * AS;
                ah[mt][0] = *reinterpret_cast<const uint32_t*>(&Ahi[r0]);
                ah[mt][1] = *reinterpret_cast<const uint32_t*>(&Ahi[r8]);
                ah[mt][2] = *reinterpret_cast<const uint32_t*>(&Ahi[r0 + 8]);
                ah[mt][3] = *reinterpret_cast<const uint32_t*>(&Ahi[r8 + 8]);
            }
#pragma unroll
            for (int nt = 0; nt < 8; nt++) {
                const int nb = (wn + nt * 8 + grp) * AS + s + qid * 2;
                uint32_t bh[2];
                bh[0] = *reinterpret_cast<const uint32_t*>(&Bhi[nb]);
                bh[1] = *reinterpret_cast<const uint32_t*>(&Bhi[nb + 8]);
#pragma unroll
                for (int mt = 0; mt < 2; mt++)
                    mma16816(acc[mt][nt], ah[mt], bh);
            }
        }
    };

    // ---- prologue: chunk 0 ----
    {
        float va[16]; uint32_t vb[8];
        loadA(0, va); loadB(0, vb);
        storeA(va);   storeB(vb);
    }
    __syncthreads();

    // ---- pipelined main loop (two syncs, single buffer — proven) ----
    for (int ch = 0; ch < NCHUNK - 1; ch++) {
        float wa[16]; uint32_t wb[8];
        loadA((ch + 1) * 32, wa);
        loadB((ch + 1) * 32, wb);
        mmaStep();
        __syncthreads();
        storeA(wa); storeB(wb);
        __syncthreads();
    }
    mmaStep();

    // ---- epilogue: bias / residual / ReLU -> bf16 outputs (+ BN stats / agg) ----
    const float ea = (MODE != 1) ? (1.0f + __ldg(epsn)) : 0.0f;   // next-layer eps
#pragma unroll
    for (int nt = 0; nt < 8; nt++) {
        const int ccl = wn + nt * 8 + qid * 2;
        const int cc  = bn + ccl;
        const float b0 = bias[cc], b1 = bias[cc + 1];
        float cs0 = 0.f, cs1 = 0.f, cq0 = 0.f, cq1 = 0.f;
#pragma unroll
        for (int mt = 0; mt < 2; mt++) {
            const int r0 = bm + wm + mt * 16 + grp;
#pragma unroll
            for (int hrow = 0; hrow < 2; hrow++) {
                const int r = r0 + hrow * 8;
                if (r < NN) {
                    float2 o;
                    o.x = acc[mt][nt][hrow * 2 + 0] + b0;
                    o.y = acc[mt][nt][hrow * 2 + 1] + b1;
                    if (MODE == 2) {     // residual from bf16 h
                        uint32_t hu = g_hb[((size_t)r * 128 + cc) >> 1];
                        o.x = fmaxf(o.x + bflo(hu), 0.f);
                        o.y = fmaxf(o.y + bfhi(hu), 0.f);
                    }
                    if (MODE == 1) {
                        cs0 += o.x; cq0 = fmaf(o.x, o.x, cq0);
                        cs1 += o.y; cq1 = fmaf(o.y, o.y, cq1);
                        g_zb[((size_t)r * 256 + cc) >> 1] = cvt2(o.x, o.y);
                    } else {
                        const uint32_t hb = cvt2(o.x, o.y);
                        const size_t half = ((size_t)r * 128 + cc) >> 1;
                        g_hb[half] = hb;
                        // fused agg init for the NEXT aggregation:
                        g_aggb[half] = cvt2(ea * bflo(hb), ea * bfhi(hb));
                    }
                }
            }
        }
        if (MODE == 1) {
            atomicAdd(&s_sum[ccl],       cs0);
            atomicAdd(&s_sum[ccl + 1],   cs1);
            atomicAdd(&s_sumsq[ccl],     cq0);
            atomicAdd(&s_sumsq[ccl + 1], cq1);
        }
    }
    if (MODE == 1) {
        __syncthreads();
        if (tid < 128) {
            atomicAdd(&g_sum[bn + tid],   (double)s_sum[tid]);
            atomicAdd(&g_sumsq[bn + tid], (double)s_sumsq[tid]);
        }
    }
}

// ---------------- small utility kernels -----------------------------------
__global__ void zero_pool_kernel() {
    int i = blockIdx.x * 256 + threadIdx.x;
    g_pool[i] = 0.f;
    if (i < 2 * GG) g_cnt[i] = 0.f;
}

// 16 threads per edge: gather 16B bf16, one v4.bf16x2 red (16B) into aggb[dst];
// block 0 zeroes the BN accumulators for the upcoming MODE1.
__global__ void scatter_kernel(const int* __restrict__ ei) {
    int idx = blockIdx.x * 256 + threadIdx.x;  // grid 100000 x 256 (== E*16)
    if (blockIdx.x == 0) { g_sum[threadIdx.x] = 0.0; g_sumsq[threadIdx.x] = 0.0; }
    int e = idx >> 4;
    int c = idx & 15;
    int src = __ldg(&ei[e]);
    int dst = __ldg(&ei[EE + e]);
    uint4 v = *reinterpret_cast<const uint4*>(&g_hb[src * 64 + c * 4]);
    uint32_t* p = &g_aggb[dst * 64 + c * 4];
    asm volatile("red.global.add.noftz.v4.bf16x2 [%0], {%1,%2,%3,%4};"
                 :: "l"(p), "r"(v.x), "r"(v.y), "r"(v.z), "r"(v.w) : "memory");
}

__global__ void pool_kernel(const int* __restrict__ batch, int which) {
    int idx = blockIdx.x * 256 + threadIdx.x;   // 12500 x 256 (== N*32)
    int n = idx >> 5;
    int c = idx & 31;
    int g = __ldg(&batch[n]);
    uint2 v = *reinterpret_cast<const uint2*>(&g_hb[n * 64 + c * 2]);
    float f0 = bflo(v.x), f1 = bfhi(v.x), f2 = bflo(v.y), f3 = bfhi(v.y);
    float* p = &g_pool[(which * GG + g) * 128 + c * 4];
    asm volatile("red.global.add.v4.f32 [%0], {%1,%2,%3,%4};"
                 :: "l"(p), "f"(f0), "f"(f1), "f"(f2), "f"(f3) : "memory");
    if ((idx & 31) == 0) atomicAdd(&g_cnt[which * GG + g], 1.0f);
}

__global__ void head1_kernel(const float* __restrict__ W, const float* __restrict__ b) {
    int g = blockIdx.x, j = threadIdx.x;   // 64 x 256
    __shared__ float xc[256];
    if (j < 128) xc[j] = g_pool[g * 128 + j] / fmaxf(g_cnt[g], 1.0f);
    else         xc[j] = g_pool[(GG + g) * 128 + (j - 128)] / fmaxf(g_cnt[GG + g], 1.0f);
    __syncthreads();
    float acc = b[j];
#pragma unroll 8
    for (int k = 0; k < 256; k++) acc = fmaf(xc[k], W[k * 256 + j], acc);
    g_fc1o[g * 256 + j] = fmaxf(acc, 0.f);
}

__global__ void head2_kernel(const float* __restrict__ W, const float* __restrict__ b) {
    int g = blockIdx.x, j = threadIdx.x;   // 64 x 64
    __shared__ float xin[256];
    for (int k = j; k < 256; k += 64) xin[k] = g_fc1o[g * 256 + k];
    __syncthreads();
    float acc = b[j];
#pragma unroll 8
    for (int k = 0; k < 256; k++) acc = fmaf(xin[k], W[k * 64 + j], acc);
    g_fc2o[g * 64 + j] = fmaxf(acc, 0.f);
}

__global__ void head3_kernel(const float* __restrict__ W, const float* __restrict__ b,
                             float* __restrict__ out) {
    int g = threadIdx.x;   // 1 x 64
    float acc = b[0];
#pragma unroll
    for (int k = 0; k < 64; k++) acc = fmaf(g_fc2o[g * 64 + k], W[k], acc);
    out[g] = 1.0f / (1.0f + expf(-acc));
}

// ---------------- orchestration -------------------------------------------
extern "C" void kernel_launch(void* const* d_in, const int* in_sizes, int n_in,
                              void* d_out, int out_size) {
    const float* x[2]     = { (const float*)d_in[0], (const float*)d_in[3] };
    const int*   ei[2]    = { (const int*)d_in[1],   (const int*)d_in[4] };
    const int*   batch[2] = { (const int*)d_in[2],   (const int*)d_in[5] };

    uint16_t *eB, *w1B, *w2B;
    cudaGetSymbolAddress((void**)&eB, g_eB);
    cudaGetSymbolAddress((void**)&w1B, g_w1B);
    cudaGetSymbolAddress((void**)&w2B, g_w2B);

    const int GRID_M = (NN + 127) / 128;   // 782

    zero_pool_kernel<<<64, 256>>>();

    for (int b = 0; b < 2; b++) {
        int o = 6 + b * 9;
        const float* embW = (const float*)d_in[o + 0];
        const float* embB = (const float*)d_in[o + 1];
        const float* W1   = (const float*)d_in[o + 2];
        const float* b1   = (const float*)d_in[o + 3];
        const float* gam  = (const float*)d_in[o + 4];
        const float* bet  = (const float*)d_in[o + 5];
        const float* W2   = (const float*)d_in[o + 6];
        const float* b2   = (const float*)d_in[o + 7];
        const float* eps  = (const float*)d_in[o + 8];

        // pre-convert this branch's weights to [n][k] bf16
        convB_kernel<<<dim3(256, 1), 256>>>(embW, eB, 1024, 128);
        convB_kernel<<<dim3(64, 4), 256>>>(W1, w1B, 128, 256);
        convB_kernel<<<dim3(64, 4), 256>>>(W2, w2B, 256, 128);

        // embedding; epilogue writes aggb = (1+eps[0])*h
        mma_gemm<0><<<dim3(GRID_M, 1), 256>>>(x[b], eB, embB, nullptr, nullptr, eps);

        for (int i = 0; i < 4; i++) {
            scatter_kernel<<<100000, 256>>>(ei[b]);
            mma_gemm<1><<<dim3(GRID_M, 2), 256>>>(nullptr, w1B + (size_t)i * 256 * 128,
                                                  b1 + i * 256, nullptr, nullptr, nullptr);
            // epilogue writes aggb = (1+eps[i+1])*h (i=3: harmless, overwritten)
            mma_gemm<2><<<dim3(GRID_M, 1), 256>>>(nullptr, w2B + (size_t)i * 128 * 256,
                                                  b2 + i * 128, gam + i * 256, bet + i * 256,
                                                  eps + ((i < 3) ? i + 1 : 3));
        }
        pool_kernel<<<12500, 256>>>(batch[b], b);
    }

    head1_kernel<<<64, 256>>>((const float*)d_in[24], (const float*)d_in[25]);
    head2_kernel<<<64, 64>>>((const float*)d_in[26], (const float*)d_in[27]);
    head3_kernel<<<1, 64>>>((const float*)d_in[28], (const float*)d_in[29], (float*)d_out);
}

// round 16
// speedup vs baseline: 1.0568x; 1.0568x over previous
#include <cuda_runtime.h>
#include <math.h>
#include <stdint.h>

#define NN 100000
#define EE 1600000
#define GG 64

// ---------------- scratch (device globals; no allocation allowed) ----------
__device__ uint32_t g_hb[2 * NN * 64];     // bf16x2 h, per branch
__device__ uint32_t g_zb[2 * NN * 128];    // bf16x2 z, per branch
__device__ uint32_t g_aggb[2 * NN * 64];   // bf16x2 agg, per branch
__device__ double   g_sum[2 * 256];
__device__ double   g_sumsq[2 * 256];
__device__ float    g_pool[2 * GG * 128];
__device__ float    g_cnt[2 * GG];
__device__ float    g_fc1o[GG * 256];
__device__ float    g_fc2o[GG * 64];
// preconverted weights, [n][k] bf16 (uint16), both branches
__device__ uint16_t g_eB[2 * 128 * 1024];
__device__ uint16_t g_w1B[2 * 4 * 256 * 128];
__device__ uint16_t g_w2B[2 * 4 * 128 * 256];

// ---------------- helpers ---------------------------------------------------
__device__ __forceinline__ uint32_t cvt2(float e0, float e1) {
    uint32_t p;
    asm("cvt.rn.bf16x2.f32 %0, %1, %2;" : "=r"(p) : "f"(e1), "f"(e0));
    return p;
}
__device__ __forceinline__ float bflo(uint32_t u) { return __uint_as_float(u << 16); }
__device__ __forceinline__ float bfhi(uint32_t u) { return __uint_as_float(u & 0xFFFF0000u); }

__device__ __forceinline__ void mma16816(float* c, const uint32_t* a, const uint32_t* b) {
    asm volatile("mma.sync.aligned.m16n8k16.row.col.f32.bf16.bf16.f32 "
                 "{%0,%1,%2,%3}, {%4,%5,%6,%7}, {%8,%9}, {%0,%1,%2,%3};"
                 : "+f"(c[0]), "+f"(c[1]), "+f"(c[2]), "+f"(c[3])
                 : "r"(a[0]), "r"(a[1]), "r"(a[2]), "r"(a[3]), "r"(b[0]), "r"(b[1]));
}

// ---------------- weight pre-conversion ------------------------------------
// src W is [K][Nn] fp32 (layer = blockIdx.y); dst H is [Nn][K] bf16
__global__ void convB_kernel(const float* __restrict__ W, uint16_t* __restrict__ H,
                             int K, int Nn) {
    const float* src = W + (size_t)blockIdx.y * K * Nn;
    uint32_t* dh = reinterpret_cast<uint32_t*>(H) + (size_t)blockIdx.y * (K * Nn / 2);
    int idx = blockIdx.x * 256 + threadIdx.x;          // over (K/2)*Nn
    if (idx >= (K / 2) * Nn) return;
    int k2 = idx / Nn, n = idx - k2 * Nn;
    float e0 = __ldg(&src[(size_t)(2 * k2) * Nn + n]);
    float e1 = __ldg(&src[(size_t)(2 * k2 + 1) * Nn + n]);
    dh[(size_t)n * (K / 2) + k2] = cvt2(e0, e1);
}

// ---------------- bf16 mma.sync GEMM (R14 loop, branch-merged) --------------
// blockIdx.z = branch. MODE 0: hb = bf16(x @ B + bias)
// MODE 1: zb = bf16(aggb @ B + bias)   (grid.y=2; BN stats fp32, per branch)
// MODE 2: hb = bf16(relu(relu(BN(zb)) @ B + bias + hb))
#define AS 40   // smem row stride in bf16 elems (80 B)

template <int MODE>
__global__ __launch_bounds__(256, 2)
void mma_gemm(const float* __restrict__ A0, const float* __restrict__ A1,
              const uint16_t* __restrict__ BH,
              const float* __restrict__ bias0, const float* __restrict__ bias1,
              const float* __restrict__ gam0, const float* __restrict__ gam1,
              const float* __restrict__ bet0, const float* __restrict__ bet1)
{
    constexpr int K = (MODE == 0) ? 1024 : ((MODE == 1) ? 128 : 256);
    constexpr int NCHUNK = K / 32;
    constexpr size_t BSTRIDE = (MODE == 0) ? (size_t)128 * 1024
                              : ((MODE == 1) ? (size_t)4 * 256 * 128
                                             : (size_t)4 * 128 * 256);

    __shared__ __align__(16) uint16_t Ahi[128 * AS];
    __shared__ __align__(16) uint16_t Bhi[128 * AS];
    __shared__ float s_sum[128], s_sumsq[128];
    __shared__ float s_scale[256], s_shift[256];

    const int tid  = threadIdx.x;
    const int lane = tid & 31, wid = tid >> 5;
    const int br = blockIdx.z;
    const int bm = blockIdx.x * 128;
    const int bn = blockIdx.y * 128;
    const int wm = (wid >> 1) * 32;
    const int wn = (wid & 1) * 64;
    const int grp = lane >> 2, qid = lane & 3;

    const float* bias = br ? bias1 : bias0;
    const uint16_t* BHp = BH + (size_t)br * BSTRIDE;
    uint32_t* hbP  = g_hb   + (size_t)br * NN * 64;
    uint32_t* zbP  = g_zb   + (size_t)br * NN * 128;
    uint32_t* aggP = g_aggb + (size_t)br * NN * 64;

    if (MODE == 1 && tid < 128) { s_sum[tid] = 0.f; s_sumsq[tid] = 0.f; }
    if (MODE == 2) {   // fused bn_finalize, per-branch stats
        float mean = (float)(g_sum[br * 256 + tid] / (double)NN);
        float var  = (float)(g_sumsq[br * 256 + tid] / (double)NN) - mean * mean;
        const float* gm = br ? gam1 : gam0;
        const float* bt = br ? bet1 : bet0;
        float sc = __ldg(&gm[tid]) * rsqrtf(var + 1e-5f);
        s_scale[tid] = sc;
        s_shift[tid] = fmaf(-mean, sc, __ldg(&bt[tid]));
        __syncthreads();
    }

    float acc[2][8][4];
#pragma unroll
    for (int mt = 0; mt < 2; mt++)
#pragma unroll
        for (int nt = 0; nt < 8; nt++)
#pragma unroll
            for (int q = 0; q < 4; q++) acc[mt][nt][q] = 0.f;

    const int arow = tid >> 1, ahalf = tid & 1;
    const int bnid = tid & 127, bkh = (tid >> 7) * 16;
    const int rA = bm + arow;

    auto loadA = [&](int k0, float* v) {
        if (rA < NN) {
            if (MODE == 2) {
                const uint32_t* zp = zbP + ((size_t)rA * 256 + k0 + ahalf * 16) / 2;
                uint32_t u[8];
                *reinterpret_cast<uint4*>(u)     = __ldg(reinterpret_cast<const uint4*>(zp));
                *reinterpret_cast<uint4*>(u + 4) = __ldg(reinterpret_cast<const uint4*>(zp + 4));
                const int kb = k0 + ahalf * 16;
#pragma unroll
                for (int j = 0; j < 8; j++) {
                    v[2 * j + 0] = fmaxf(fmaf(bflo(u[j]), s_scale[kb + 2 * j],     s_shift[kb + 2 * j]), 0.f);
                    v[2 * j + 1] = fmaxf(fmaf(bfhi(u[j]), s_scale[kb + 2 * j + 1], s_shift[kb + 2 * j + 1]), 0.f);
                }
            } else if (MODE == 1) {
                const uint32_t* ap = aggP + ((size_t)rA * 128 + k0 + ahalf * 16) / 2;
                uint32_t u[8];
                *reinterpret_cast<uint4*>(u)     = __ldg(reinterpret_cast<const uint4*>(ap));
                *reinterpret_cast<uint4*>(u + 4) = __ldg(reinterpret_cast<const uint4*>(ap + 4));
#pragma unroll
                for (int j = 0; j < 8; j++) {
                    v[2 * j + 0] = bflo(u[j]);
                    v[2 * j + 1] = bfhi(u[j]);
                }
            } else {
                const float* ap = (br ? A1 : A0) + (size_t)rA * K + k0 + ahalf * 16;
#pragma unroll
                for (int q = 0; q < 4; q++)
                    *reinterpret_cast<float4*>(v + 4 * q) =
                        __ldg(reinterpret_cast<const float4*>(ap + 4 * q));
            }
        } else {
#pragma unroll
            for (int j = 0; j < 16; j++) v[j] = 0.f;
        }
    };
    auto loadB = [&](int k0, uint32_t* vb) {
        const uint32_t* ph = reinterpret_cast<const uint32_t*>(BHp) +
                             ((size_t)(bn + bnid) * K + k0 + bkh) / 2;
        *reinterpret_cast<uint4*>(vb)     = __ldg(reinterpret_cast<const uint4*>(ph));
        *reinterpret_cast<uint4*>(vb + 4) = __ldg(reinterpret_cast<const uint4*>(ph + 4));
    };
    auto storeA = [&](const float* v) {
#pragma unroll
        for (int q = 0; q < 2; q++) {
            uint32_t hs[4];
#pragma unroll
            for (int p = 0; p < 4; p++)
                hs[p] = cvt2(v[q * 8 + p * 2], v[q * 8 + p * 2 + 1]);
            const int c = ahalf * 16 + q * 8;
            *reinterpret_cast<uint4*>(&Ahi[arow * AS + c]) = make_uint4(hs[0], hs[1], hs[2], hs[3]);
        }
    };
    auto storeB = [&](const uint32_t* vb) {
        *reinterpret_cast<uint4*>(&Bhi[bnid * AS + bkh])     = *reinterpret_cast<const uint4*>(vb);
        *reinterpret_cast<uint4*>(&Bhi[bnid * AS + bkh + 8]) = *reinterpret_cast<const uint4*>(vb + 4);
    };
    auto mmaStep = [&]() {
#pragma unroll
        for (int s = 0; s < 32; s += 16) {
            uint32_t ah[2][4];
#pragma unroll
            for (int mt = 0; mt < 2; mt++) {
                const int r0 = (wm + mt * 16 + grp) * AS + s + qid * 2;
                const int r8 = r0 + 8 * AS;
                ah[mt][0] = *reinterpret_cast<const uint32_t*>(&Ahi[r0]);
                ah[mt][1] = *reinterpret_cast<const uint32_t*>(&Ahi[r8]);
                ah[mt][2] = *reinterpret_cast<const uint32_t*>(&Ahi[r0 + 8]);
                ah[mt][3] = *reinterpret_cast<const uint32_t*>(&Ahi[r8 + 8]);
            }
#pragma unroll
            for (int nt = 0; nt < 8; nt++) {
                const int nb = (wn + nt * 8 + grp) * AS + s + qid * 2;
                uint32_t bh[2];
                bh[0] = *reinterpret_cast<const uint32_t*>(&Bhi[nb]);
                bh[1] = *reinterpret_cast<const uint32_t*>(&Bhi[nb + 8]);
#pragma unroll
                for (int mt = 0; mt < 2; mt++)
                    mma16816(acc[mt][nt], ah[mt], bh);
            }
        }
    };

    // ---- prologue: chunk 0 ----
    {
        float va[16]; uint32_t vb[8];
        loadA(0, va); loadB(0, vb);
        storeA(va);   storeB(vb);
    }
    __syncthreads();

    // ---- pipelined main loop (two syncs, single buffer — proven) ----
    for (int ch = 0; ch < NCHUNK - 1; ch++) {
        float wa[16]; uint32_t wb[8];
        loadA((ch + 1) * 32, wa);
        loadB((ch + 1) * 32, wb);
        mmaStep();
        __syncthreads();
        storeA(wa); storeB(wb);
        __syncthreads();
    }
    mmaStep();

    // ---- epilogue: bias / residual / ReLU -> bf16 outputs (+ BN stats) ----
#pragma unroll
    for (int nt = 0; nt < 8; nt++) {
        const int ccl = wn + nt * 8 + qid * 2;
        const int cc  = bn + ccl;
        const float b0 = bias[cc], b1 = bias[cc + 1];
        float cs0 = 0.f, cs1 = 0.f, cq0 = 0.f, cq1 = 0.f;
#pragma unroll
        for (int mt = 0; mt < 2; mt++) {
            const int r0 = bm + wm + mt * 16 + grp;
#pragma unroll
            for (int hrow = 0; hrow < 2; hrow++) {
                const int r = r0 + hrow * 8;
                if (r < NN) {
                    float2 o;
                    o.x = acc[mt][nt][hrow * 2 + 0] + b0;
                    o.y = acc[mt][nt][hrow * 2 + 1] + b1;
                    if (MODE == 2) {
                        uint32_t hu = hbP[((size_t)r * 128 + cc) >> 1];
                        o.x = fmaxf(o.x + bflo(hu), 0.f);
                        o.y = fmaxf(o.y + bfhi(hu), 0.f);
                    }
                    if (MODE == 1) {
                        cs0 += o.x; cq0 = fmaf(o.x, o.x, cq0);
                        cs1 += o.y; cq1 = fmaf(o.y, o.y, cq1);
                        zbP[((size_t)r * 256 + cc) >> 1] = cvt2(o.x, o.y);
                    } else {
                        hbP[((size_t)r * 128 + cc) >> 1] = cvt2(o.x, o.y);
                    }
                }
            }
        }
        if (MODE == 1) {
            atomicAdd(&s_sum[ccl],       cs0);
            atomicAdd(&s_sum[ccl + 1],   cs1);
            atomicAdd(&s_sumsq[ccl],     cq0);
            atomicAdd(&s_sumsq[ccl + 1], cq1);
        }
    }
    if (MODE == 1) {
        __syncthreads();
        if (tid < 128) {
            atomicAdd(&g_sum[br * 256 + bn + tid],   (double)s_sum[tid]);
            atomicAdd(&g_sumsq[br * 256 + bn + tid], (double)s_sumsq[tid]);
        }
    }
}

// ---------------- small utility kernels -----------------------------------
__global__ void zero_pool_kernel() {
    int i = blockIdx.x * 256 + threadIdx.x;
    g_pool[i] = 0.f;
    if (i < 2 * GG) g_cnt[i] = 0.f;
}

// g_aggb = bf16((1+eps)*hb); block 0 zeroes BN accumulators. grid (6250, 2)
__global__ void init_agg_kernel(const float* __restrict__ e0,
                                const float* __restrict__ e1) {
    const int br = blockIdx.y;
    int i = blockIdx.x * 256 + threadIdx.x;
    if (blockIdx.x == 0) { g_sum[br * 256 + threadIdx.x] = 0.0;
                           g_sumsq[br * 256 + threadIdx.x] = 0.0; }
    float e = 1.0f + __ldg(br ? e1 : e0);
    const uint32_t* hb = g_hb + (size_t)br * NN * 64;
    uint32_t* agg = g_aggb + (size_t)br * NN * 64;
    uint4 v = *reinterpret_cast<const uint4*>(&hb[i * 4]);
    uint4 o;
    o.x = cvt2(e * bflo(v.x), e * bfhi(v.x));
    o.y = cvt2(e * bflo(v.y), e * bfhi(v.y));
    o.z = cvt2(e * bflo(v.z), e * bfhi(v.z));
    o.w = cvt2(e * bflo(v.w), e * bfhi(v.w));
    *reinterpret_cast<uint4*>(&agg[i * 4]) = o;
}

// 16 threads per edge, grid (100000, 2): branch-merged bf16 scatter
__global__ void scatter_kernel(const int* __restrict__ ei0,
                               const int* __restrict__ ei1) {
    const int br = blockIdx.y;
    const int* ei = br ? ei1 : ei0;
    int idx = blockIdx.x * 256 + threadIdx.x;
    int e = idx >> 4;
    int c = idx & 15;
    int src = __ldg(&ei[e]);
    int dst = __ldg(&ei[EE + e]);
    const uint32_t* hb = g_hb + (size_t)br * NN * 64;
    uint32_t* agg = g_aggb + (size_t)br * NN * 64;
    uint4 v = *reinterpret_cast<const uint4*>(&hb[src * 64 + c * 4]);
    uint32_t* p = &agg[dst * 64 + c * 4];
    asm volatile("red.global.add.noftz.v4.bf16x2 [%0], {%1,%2,%3,%4};"
                 :: "l"(p), "r"(v.x), "r"(v.y), "r"(v.z), "r"(v.w) : "memory");
}

// grid (12500, 2): branch-merged pool
__global__ void pool_kernel(const int* __restrict__ b0, const int* __restrict__ b1) {
    const int br = blockIdx.y;
    const int* batch = br ? b1 : b0;
    int idx = blockIdx.x * 256 + threadIdx.x;
    int n = idx >> 5;
    int c = idx & 31;
    int g = __ldg(&batch[n]);
    const uint32_t* hb = g_hb + (size_t)br * NN * 64;
    uint2 v = *reinterpret_cast<const uint2*>(&hb[n * 64 + c * 2]);
    float f0 = bflo(v.x), f1 = bfhi(v.x), f2 = bflo(v.y), f3 = bfhi(v.y);
    float* p = &g_pool[(br * GG + g) * 128 + c * 4];
    asm volatile("red.global.add.v4.f32 [%0], {%1,%2,%3,%4};"
                 :: "l"(p), "f"(f0), "f"(f1), "f"(f2), "f"(f3) : "memory");
    if ((idx & 31) == 0) atomicAdd(&g_cnt[br * GG + g], 1.0f);
}

__global__ void head1_kernel(const float* __restrict__ W, const float* __restrict__ b) {
    int g = blockIdx.x, j = threadIdx.x;   // 64 x 256
    __shared__ float xc[256];
    if (j < 128) xc[j] = g_pool[g * 128 + j] / fmaxf(g_cnt[g], 1.0f);
    else         xc[j] = g_pool[(GG + g) * 128 + (j - 128)] / fmaxf(g_cnt[GG + g], 1.0f);
    __syncthreads();
    float acc = b[j];
#pragma unroll 8
    for (int k = 0; k < 256; k++) acc = fmaf(xc[k], W[k * 256 + j], acc);
    g_fc1o[g * 256 + j] = fmaxf(acc, 0.f);
}

__global__ void head2_kernel(const float* __restrict__ W, const float* __restrict__ b) {
    int g = blockIdx.x, j = threadIdx.x;   // 64 x 64
    __shared__ float xin[256];
    for (int k = j; k < 256; k += 64) xin[k] = g_fc1o[g * 256 + k];
    __syncthreads();
    float acc = b[j];
#pragma unroll 8
    for (int k = 0; k < 256; k++) acc = fmaf(xin[k], W[k * 64 + j], acc);
    g_fc2o[g * 64 + j] = fmaxf(acc, 0.f);
}

__global__ void head3_kernel(const float* __restrict__ W, const float* __restrict__ b,
                             float* __restrict__ out) {
    int g = threadIdx.x;   // 1 x 64
    float acc = b[0];
#pragma unroll
    for (int k = 0; k < 64; k++) acc = fmaf(g_fc2o[g * 64 + k], W[k], acc);
    out[g] = 1.0f / (1.0f + expf(-acc));
}

// ---------------- orchestration -------------------------------------------
extern "C" void kernel_launch(void* const* d_in, const int* in_sizes, int n_in,
                              void* d_out, int out_size) {
    const float* x[2]     = { (const float*)d_in[0], (const float*)d_in[3] };
    const int*   ei[2]    = { (const int*)d_in[1],   (const int*)d_in[4] };
    const int*   batch[2] = { (const int*)d_in[2],   (const int*)d_in[5] };
    const float *embW[2], *embB[2], *W1[2], *b1[2], *gam[2], *bet[2], *W2[2], *b2[2], *eps[2];
    for (int b = 0; b < 2; b++) {
        int o = 6 + b * 9;
        embW[b] = (const float*)d_in[o + 0];
        embB[b] = (const float*)d_in[o + 1];
        W1[b]   = (const float*)d_in[o + 2];
        b1[b]   = (const float*)d_in[o + 3];
        gam[b]  = (const float*)d_in[o + 4];
        bet[b]  = (const float*)d_in[o + 5];
        W2[b]   = (const float*)d_in[o + 6];
        b2[b]   = (const float*)d_in[o + 7];
        eps[b]  = (const float*)d_in[o + 8];
    }

    uint16_t *eB, *w1B, *w2B;
    cudaGetSymbolAddress((void**)&eB, g_eB);
    cudaGetSymbolAddress((void**)&w1B, g_w1B);
    cudaGetSymbolAddress((void**)&w2B, g_w2B);

    const int GRID_M = (NN + 127) / 128;   // 782

    zero_pool_kernel<<<64, 256>>>();

    // pre-convert both branches' weights
    for (int b = 0; b < 2; b++) {
        convB_kernel<<<dim3(256, 1), 256>>>(embW[b], eB + (size_t)b * 128 * 1024, 1024, 128);
        convB_kernel<<<dim3(64, 4), 256>>>(W1[b], w1B + (size_t)b * 4 * 256 * 128, 128, 256);
        convB_kernel<<<dim3(64, 4), 256>>>(W2[b], w2B + (size_t)b * 4 * 128 * 256, 256, 128);
    }

    // embedding, both branches in one launch
    mma_gemm<0><<<dim3(GRID_M, 1, 2), 256>>>(x[0], x[1], eB, embB[0], embB[1],
                                             nullptr, nullptr, nullptr, nullptr);

    for (int i = 0; i < 4; i++) {
        init_agg_kernel<<<dim3(6250, 2), 256>>>(eps[0] + i, eps[1] + i);
        scatter_kernel<<<dim3(100000, 2), 256>>>(ei[0], ei[1]);
        mma_gemm<1><<<dim3(GRID_M, 2, 2), 256>>>(nullptr, nullptr,
            w1B + (size_t)i * 256 * 128, b1[0] + i * 256, b1[1] + i * 256,
            nullptr, nullptr, nullptr, nullptr);
        mma_gemm<2><<<dim3(GRID_M, 1, 2), 256>>>(nullptr, nullptr,
            w2B + (size_t)i * 128 * 256, b2[0] + i * 128, b2[1] + i * 128,
            gam[0] + i * 256, gam[1] + i * 256, bet[0] + i * 256, bet[1] + i * 256);
    }
    pool_kernel<<<dim3(12500, 2), 256>>>(batch[0], batch[1]);

    head1_kernel<<<64, 256>>>((const float*)d_in[24], (const float*)d_in[25]);
    head2_kernel<<<64, 64>>>((const float*)d_in[26], (const float*)d_in[27]);
    head3_kernel<<<1, 64>>>((const float*)d_in[28], (const float*)d_in[29], (float*)d_out);
}

// round 17
// speedup vs baseline: 1.1050x; 1.0457x over previous
#include <cuda_runtime.h>
#include <math.h>
#include <stdint.h>

#define NN 100000
#define EE 1600000
#define GG 64

// ---------------- scratch (device globals; no allocation allowed) ----------
__device__ uint32_t g_hb[2 * NN * 64];     // bf16x2 h, per branch
__device__ uint32_t g_zb[2 * NN * 128];    // bf16x2 z, per branch
__device__ uint32_t g_aggb[2 * NN * 64];   // bf16x2 agg, per branch
__device__ double   g_sum[2 * 256];
__device__ double   g_sumsq[2 * 256];
__device__ float    g_pool[2 * GG * 128];
__device__ float    g_cnt[2 * GG];
__device__ float    g_fc1o[GG * 256];
__device__ float    g_fc2o[GG * 64];
// preconverted weights, [n][k] bf16 (uint16), both branches
__device__ uint16_t g_eB[2 * 128 * 1024];
__device__ uint16_t g_w1B[2 * 4 * 256 * 128];
__device__ uint16_t g_w2B[2 * 4 * 128 * 256];

// ---------------- helpers ---------------------------------------------------
__device__ __forceinline__ uint32_t cvt2(float e0, float e1) {
    uint32_t p;
    asm("cvt.rn.bf16x2.f32 %0, %1, %2;" : "=r"(p) : "f"(e1), "f"(e0));
    return p;
}
__device__ __forceinline__ float bflo(uint32_t u) { return __uint_as_float(u << 16); }
__device__ __forceinline__ float bfhi(uint32_t u) { return __uint_as_float(u & 0xFFFF0000u); }

__device__ __forceinline__ void mma16816(float* c, const uint32_t* a, const uint32_t* b) {
    asm volatile("mma.sync.aligned.m16n8k16.row.col.f32.bf16.bf16.f32 "
                 "{%0,%1,%2,%3}, {%4,%5,%6,%7}, {%8,%9}, {%0,%1,%2,%3};"
                 : "+f"(c[0]), "+f"(c[1]), "+f"(c[2]), "+f"(c[3])
                 : "r"(a[0]), "r"(a[1]), "r"(a[2]), "r"(a[3]), "r"(b[0]), "r"(b[1]));
}

// ---------------- merged weight pre-conversion ------------------------------
// grid (768, 2): bx in [0,256) -> embW, [256,512) -> W1 (4 layers), [512,768) -> W2
__global__ void convAll_kernel(const float* __restrict__ e0, const float* __restrict__ e1,
                               const float* __restrict__ W10, const float* __restrict__ W11,
                               const float* __restrict__ W20, const float* __restrict__ W21) {
    const int br = blockIdx.y;
    const int bx = blockIdx.x;
    const float* src;
    uint32_t* dh;
    int K, Nn, lidx;
    if (bx < 256) {
        K = 1024; Nn = 128;
        src = br ? e1 : e0;
        dh  = reinterpret_cast<uint32_t*>(g_eB) + (size_t)br * (128 * 1024 / 2);
        lidx = bx * 256 + threadIdx.x;
    } else if (bx < 512) {
        K = 128; Nn = 256;
        const int layer = (bx - 256) >> 6;            // 64 blocks per layer
        src = (br ? W11 : W10) + (size_t)layer * K * Nn;
        dh  = reinterpret_cast<uint32_t*>(g_w1B) + (size_t)br * (4 * 256 * 128 / 2)
              + (size_t)layer * (256 * 128 / 2);
        lidx = ((bx - 256) & 63) * 256 + threadIdx.x;
    } else {
        K = 256; Nn = 128;
        const int layer = (bx - 512) >> 6;
        src = (br ? W21 : W20) + (size_t)layer * K * Nn;
        dh  = reinterpret_cast<uint32_t*>(g_w2B) + (size_t)br * (4 * 128 * 256 / 2)
              + (size_t)layer * (128 * 256 / 2);
        lidx = ((bx - 512) & 63) * 256 + threadIdx.x;
    }
    if (lidx >= (K / 2) * Nn) return;
    const int k2 = lidx / Nn, n = lidx - k2 * Nn;
    const float v0 = __ldg(&src[(size_t)(2 * k2) * Nn + n]);
    const float v1 = __ldg(&src[(size_t)(2 * k2 + 1) * Nn + n]);
    dh[(size_t)n * (K / 2) + k2] = cvt2(v0, v1);
}

// ---------------- bf16 mma.sync GEMM (R16 loop, branch-merged, opt. pool) ----
// blockIdx.z = branch. MODE 0: hb = bf16(x @ B + bias)
// MODE 1: zb = bf16(aggb @ B + bias)   (grid.y=2; BN stats fp32, per branch)
// MODE 2: h = relu(relu(BN(zb)) @ B + bias + hb);
//          POOL==0: hb = bf16(h);  POOL==1: red-add h into g_pool (no hb store)
#define AS 40   // smem row stride in bf16 elems (80 B)

template <int MODE, int POOL>
__global__ __launch_bounds__(256, 2)
void mma_gemm(const float* __restrict__ A0, const float* __restrict__ A1,
              const uint16_t* __restrict__ BH,
              const float* __restrict__ bias0, const float* __restrict__ bias1,
              const float* __restrict__ gam0, const float* __restrict__ gam1,
              const float* __restrict__ bet0, const float* __restrict__ bet1,
              const int* __restrict__ batch0, const int* __restrict__ batch1)
{
    constexpr int K = (MODE == 0) ? 1024 : ((MODE == 1) ? 128 : 256);
    constexpr int NCHUNK = K / 32;
    constexpr size_t BSTRIDE = (MODE == 0) ? (size_t)128 * 1024
                              : ((MODE == 1) ? (size_t)4 * 256 * 128
                                             : (size_t)4 * 128 * 256);

    __shared__ __align__(16) uint16_t Ahi[128 * AS];
    __shared__ __align__(16) uint16_t Bhi[128 * AS];
    __shared__ float s_sum[128], s_sumsq[128];
    __shared__ float s_scale[256], s_shift[256];

    const int tid  = threadIdx.x;
    const int lane = tid & 31, wid = tid >> 5;
    const int br = blockIdx.z;
    const int bm = blockIdx.x * 128;
    const int bn = blockIdx.y * 128;
    const int wm = (wid >> 1) * 32;
    const int wn = (wid & 1) * 64;
    const int grp = lane >> 2, qid = lane & 3;

    const float* bias = br ? bias1 : bias0;
    const uint16_t* BHp = BH + (size_t)br * BSTRIDE;
    uint32_t* hbP  = g_hb   + (size_t)br * NN * 64;
    uint32_t* zbP  = g_zb   + (size_t)br * NN * 128;
    uint32_t* aggP = g_aggb + (size_t)br * NN * 64;

    if (MODE == 1 && tid < 128) { s_sum[tid] = 0.f; s_sumsq[tid] = 0.f; }
    if (MODE == 2) {   // fused bn_finalize, per-branch stats
        float mean = (float)(g_sum[br * 256 + tid] / (double)NN);
        float var  = (float)(g_sumsq[br * 256 + tid] / (double)NN) - mean * mean;
        const float* gm = br ? gam1 : gam0;
        const float* bt = br ? bet1 : bet0;
        float sc = __ldg(&gm[tid]) * rsqrtf(var + 1e-5f);
        s_scale[tid] = sc;
        s_shift[tid] = fmaf(-mean, sc, __ldg(&bt[tid]));
        __syncthreads();
    }

    float acc[2][8][4];
#pragma unroll
    for (int mt = 0; mt < 2; mt++)
#pragma unroll
        for (int nt = 0; nt < 8; nt++)
#pragma unroll
            for (int q = 0; q < 4; q++) acc[mt][nt][q] = 0.f;

    const int arow = tid >> 1, ahalf = tid & 1;
    const int bnid = tid & 127, bkh = (tid >> 7) * 16;
    const int rA = bm + arow;

    auto loadA = [&](int k0, float* v) {
        if (rA < NN) {
            if (MODE == 2) {
                const uint32_t* zp = zbP + ((size_t)rA * 256 + k0 + ahalf * 16) / 2;
                uint32_t u[8];
                *reinterpret_cast<uint4*>(u)     = __ldg(reinterpret_cast<const uint4*>(zp));
                *reinterpret_cast<uint4*>(u + 4) = __ldg(reinterpret_cast<const uint4*>(zp + 4));
                const int kb = k0 + ahalf * 16;
#pragma unroll
                for (int j = 0; j < 8; j++) {
                    v[2 * j + 0] = fmaxf(fmaf(bflo(u[j]), s_scale[kb + 2 * j],     s_shift[kb + 2 * j]), 0.f);
                    v[2 * j + 1] = fmaxf(fmaf(bfhi(u[j]), s_scale[kb + 2 * j + 1], s_shift[kb + 2 * j + 1]), 0.f);
                }
            } else if (MODE == 1) {
                const uint32_t* ap = aggP + ((size_t)rA * 128 + k0 + ahalf * 16) / 2;
                uint32_t u[8];
                *reinterpret_cast<uint4*>(u)     = __ldg(reinterpret_cast<const uint4*>(ap));
                *reinterpret_cast<uint4*>(u + 4) = __ldg(reinterpret_cast<const uint4*>(ap + 4));
#pragma unroll
                for (int j = 0; j < 8; j++) {
                    v[2 * j + 0] = bflo(u[j]);
                    v[2 * j + 1] = bfhi(u[j]);
                }
            } else {
                const float* ap = (br ? A1 : A0) + (size_t)rA * K + k0 + ahalf * 16;
#pragma unroll
                for (int q = 0; q < 4; q++)
                    *reinterpret_cast<float4*>(v + 4 * q) =
                        __ldg(reinterpret_cast<const float4*>(ap + 4 * q));
            }
        } else {
#pragma unroll
            for (int j = 0; j < 16; j++) v[j] = 0.f;
        }
    };
    auto loadB = [&](int k0, uint32_t* vb) {
        const uint32_t* ph = reinterpret_cast<const uint32_t*>(BHp) +
                             ((size_t)(bn + bnid) * K + k0 + bkh) / 2;
        *reinterpret_cast<uint4*>(vb)     = __ldg(reinterpret_cast<const uint4*>(ph));
        *reinterpret_cast<uint4*>(vb + 4) = __ldg(reinterpret_cast<const uint4*>(ph + 4));
    };
    auto storeA = [&](const float* v) {
#pragma unroll
        for (int q = 0; q < 2; q++) {
            uint32_t hs[4];
#pragma unroll
            for (int p = 0; p < 4; p++)
                hs[p] = cvt2(v[q * 8 + p * 2], v[q * 8 + p * 2 + 1]);
            const int c = ahalf * 16 + q * 8;
            *reinterpret_cast<uint4*>(&Ahi[arow * AS + c]) = make_uint4(hs[0], hs[1], hs[2], hs[3]);
        }
    };
    auto storeB = [&](const uint32_t* vb) {
        *reinterpret_cast<uint4*>(&Bhi[bnid * AS + bkh])     = *reinterpret_cast<const uint4*>(vb);
        *reinterpret_cast<uint4*>(&Bhi[bnid * AS + bkh + 8]) = *reinterpret_cast<const uint4*>(vb + 4);
    };
    auto mmaStep = [&]() {
#pragma unroll
        for (int s = 0; s < 32; s += 16) {
            uint32_t ah[2][4];
#pragma unroll
            for (int mt = 0; mt < 2; mt++) {
                const int r0 = (wm + mt * 16 + grp) * AS + s + qid * 2;
                const int r8 = r0 + 8 * AS;
                ah[mt][0] = *reinterpret_cast<const uint32_t*>(&Ahi[r0]);
                ah[mt][1] = *reinterpret_cast<const uint32_t*>(&Ahi[r8]);
                ah[mt][2] = *reinterpret_cast<const uint32_t*>(&Ahi[r0 + 8]);
                ah[mt][3] = *reinterpret_cast<const uint32_t*>(&Ahi[r8 + 8]);
            }
#pragma unroll
            for (int nt = 0; nt < 8; nt++) {
                const int nb = (wn + nt * 8 + grp) * AS + s + qid * 2;
                uint32_t bh[2];
                bh[0] = *reinterpret_cast<const uint32_t*>(&Bhi[nb]);
                bh[1] = *reinterpret_cast<const uint32_t*>(&Bhi[nb + 8]);
#pragma unroll
                for (int mt = 0; mt < 2; mt++)
                    mma16816(acc[mt][nt], ah[mt], bh);
            }
        }
    };

    // ---- prologue: chunk 0 ----
    {
        float va[16]; uint32_t vb[8];
        loadA(0, va); loadB(0, vb);
        storeA(va);   storeB(vb);
    }
    __syncthreads();

    // ---- pipelined main loop (two syncs, single buffer — proven) ----
    for (int ch = 0; ch < NCHUNK - 1; ch++) {
        float wa[16]; uint32_t wb[8];
        loadA((ch + 1) * 32, wa);
        loadB((ch + 1) * 32, wb);
        mmaStep();
        __syncthreads();
        storeA(wa); storeB(wb);
        __syncthreads();
    }
    mmaStep();

    // ---- epilogue ----
    int gidx[2][2];
    if (MODE == 2 && POOL) {
        const int* batchP = br ? batch1 : batch0;
#pragma unroll
        for (int mt = 0; mt < 2; mt++)
#pragma unroll
            for (int hrow = 0; hrow < 2; hrow++) {
                const int r = bm + wm + mt * 16 + grp + hrow * 8;
                gidx[mt][hrow] = (r < NN) ? __ldg(&batchP[r]) : 0;
            }
    }
#pragma unroll
    for (int nt = 0; nt < 8; nt++) {
        const int ccl = wn + nt * 8 + qid * 2;
        const int cc  = bn + ccl;
        const float b0 = bias[cc], b1 = bias[cc + 1];
        float cs0 = 0.f, cs1 = 0.f, cq0 = 0.f, cq1 = 0.f;
#pragma unroll
        for (int mt = 0; mt < 2; mt++) {
            const int r0 = bm + wm + mt * 16 + grp;
#pragma unroll
            for (int hrow = 0; hrow < 2; hrow++) {
                const int r = r0 + hrow * 8;
                if (r < NN) {
                    float2 o;
                    o.x = acc[mt][nt][hrow * 2 + 0] + b0;
                    o.y = acc[mt][nt][hrow * 2 + 1] + b1;
                    if (MODE == 2) {
                        uint32_t hu = hbP[((size_t)r * 128 + cc) >> 1];
                        o.x = fmaxf(o.x + bflo(hu), 0.f);
                        o.y = fmaxf(o.y + bfhi(hu), 0.f);
                    }
                    if (MODE == 1) {
                        cs0 += o.x; cq0 = fmaf(o.x, o.x, cq0);
                        cs1 += o.y; cq1 = fmaf(o.y, o.y, cq1);
                        zbP[((size_t)r * 256 + cc) >> 1] = cvt2(o.x, o.y);
                    } else if (MODE == 2 && POOL) {
                        float* p = &g_pool[((size_t)(br * GG + gidx[mt][hrow])) * 128 + cc];
                        asm volatile("red.global.add.v2.f32 [%0], {%1,%2};"
                                     :: "l"(p), "f"(o.x), "f"(o.y) : "memory");
                    } else {
                        hbP[((size_t)r * 128 + cc) >> 1] = cvt2(o.x, o.y);
                    }
                }
            }
        }
        if (MODE == 1) {
            atomicAdd(&s_sum[ccl],       cs0);
            atomicAdd(&s_sum[ccl + 1],   cs1);
            atomicAdd(&s_sumsq[ccl],     cq0);
            atomicAdd(&s_sumsq[ccl + 1], cq1);
        }
    }
    if (MODE == 2 && POOL) {
        if (qid == 0 && (wid & 1) == 0) {
#pragma unroll
            for (int mt = 0; mt < 2; mt++)
#pragma unroll
                for (int hrow = 0; hrow < 2; hrow++) {
                    const int r = bm + wm + mt * 16 + grp + hrow * 8;
                    if (r < NN) atomicAdd(&g_cnt[br * GG + gidx[mt][hrow]], 1.0f);
                }
        }
    }
    if (MODE == 1) {
        __syncthreads();
        if (tid < 128) {
            atomicAdd(&g_sum[br * 256 + bn + tid],   (double)s_sum[tid]);
            atomicAdd(&g_sumsq[br * 256 + bn + tid], (double)s_sumsq[tid]);
        }
    }
}

// ---------------- small utility kernels -----------------------------------
__global__ void zero_pool_kernel() {
    int i = blockIdx.x * 256 + threadIdx.x;
    g_pool[i] = 0.f;
    if (i < 2 * GG) g_cnt[i] = 0.f;
}

// g_aggb = bf16((1+eps)*hb); block 0 zeroes BN accumulators. grid (6250, 2)
__global__ void init_agg_kernel(const float* __restrict__ e0,
                                const float* __restrict__ e1) {
    const int br = blockIdx.y;
    int i = blockIdx.x * 256 + threadIdx.x;
    if (blockIdx.x == 0) { g_sum[br * 256 + threadIdx.x] = 0.0;
                           g_sumsq[br * 256 + threadIdx.x] = 0.0; }
    float e = 1.0f + __ldg(br ? e1 : e0);
    const uint32_t* hb = g_hb + (size_t)br * NN * 64;
    uint32_t* agg = g_aggb + (size_t)br * NN * 64;
    uint4 v = *reinterpret_cast<const uint4*>(&hb[i * 4]);
    uint4 o;
    o.x = cvt2(e * bflo(v.x), e * bfhi(v.x));
    o.y = cvt2(e * bflo(v.y), e * bfhi(v.y));
    o.z = cvt2(e * bflo(v.z), e * bfhi(v.z));
    o.w = cvt2(e * bflo(v.w), e * bfhi(v.w));
    *reinterpret_cast<uint4*>(&agg[i * 4]) = o;
}

// 16 threads per edge, grid (100000, 2): branch-merged bf16 scatter
__global__ void scatter_kernel(const int* __restrict__ ei0,
                               const int* __restrict__ ei1) {
    const int br = blockIdx.y;
    const int* ei = br ? ei1 : ei0;
    int idx = blockIdx.x * 256 + threadIdx.x;
    int e = idx >> 4;
    int c = idx & 15;
    int src = __ldg(&ei[e]);
    int dst = __ldg(&ei[EE + e]);
    const uint32_t* hb = g_hb + (size_t)br * NN * 64;
    uint32_t* agg = g_aggb + (size_t)br * NN * 64;
    uint4 v = *reinterpret_cast<const uint4*>(&hb[src * 64 + c * 4]);
    uint32_t* p = &agg[dst * 64 + c * 4];
    asm volatile("red.global.add.noftz.v4.bf16x2 [%0], {%1,%2,%3,%4};"
                 :: "l"(p), "r"(v.x), "r"(v.y), "r"(v.z), "r"(v.w) : "memory");
}

__global__ void head1_kernel(const float* __restrict__ W, const float* __restrict__ b) {
    int g = blockIdx.x, j = threadIdx.x;   // 64 x 256
    __shared__ float xc[256];
    if (j < 128) xc[j] = g_pool[g * 128 + j] / fmaxf(g_cnt[g], 1.0f);
    else         xc[j] = g_pool[(GG + g) * 128 + (j - 128)] / fmaxf(g_cnt[GG + g], 1.0f);
    __syncthreads();
    float acc = b[j];
#pragma unroll 8
    for (int k = 0; k < 256; k++) acc = fmaf(xc[k], W[k * 256 + j], acc);
    g_fc1o[g * 256 + j] = fmaxf(acc, 0.f);
}

__global__ void head2_kernel(const float* __restrict__ W, const float* __restrict__ b) {
    int g = blockIdx.x, j = threadIdx.x;   // 64 x 64
    __shared__ float xin[256];
    for (int k = j; k < 256; k += 64) xin[k] = g_fc1o[g * 256 + k];
    __syncthreads();
    float acc = b[j];
#pragma unroll 8
    for (int k = 0; k < 256; k++) acc = fmaf(xin[k], W[k * 64 + j], acc);
    g_fc2o[g * 64 + j] = fmaxf(acc, 0.f);
}

__global__ void head3_kernel(const float* __restrict__ W, const float* __restrict__ b,
                             float* __restrict__ out) {
    int g = threadIdx.x;   // 1 x 64
    float acc = b[0];
#pragma unroll
    for (int k = 0; k < 64; k++) acc = fmaf(g_fc2o[g * 64 + k], W[k], acc);
    out[g] = 1.0f / (1.0f + expf(-acc));
}

// ---------------- orchestration -------------------------------------------
extern "C" void kernel_launch(void* const* d_in, const int* in_sizes, int n_in,
                              void* d_out, int out_size) {
    const float* x[2]     = { (const float*)d_in[0], (const float*)d_in[3] };
    const int*   ei[2]    = { (const int*)d_in[1],   (const int*)d_in[4] };
    const int*   batch[2] = { (const int*)d_in[2],   (const int*)d_in[5] };
    const float *embW[2], *embB[2], *W1[2], *b1[2], *gam[2], *bet[2], *W2[2], *b2[2], *eps[2];
    for (int b = 0; b < 2; b++) {
        int o = 6 + b * 9;
        embW[b] = (const float*)d_in[o + 0];
        embB[b] = (const float*)d_in[o + 1];
        W1[b]   = (const float*)d_in[o + 2];
        b1[b]   = (const float*)d_in[o + 3];
        gam[b]  = (const float*)d_in[o + 4];
        bet[b]  = (const float*)d_in[o + 5];
        W2[b]   = (const float*)d_in[o + 6];
        b2[b]   = (const float*)d_in[o + 7];
        eps[b]  = (const float*)d_in[o + 8];
    }

    uint16_t *eB, *w1B, *w2B;
    cudaGetSymbolAddress((void**)&eB, g_eB);
    cudaGetSymbolAddress((void**)&w1B, g_w1B);
    cudaGetSymbolAddress((void**)&w2B, g_w2B);

    const int GRID_M = (NN + 127) / 128;   // 782

    zero_pool_kernel<<<64, 256>>>();

    // pre-convert both branches' weights in ONE launch
    convAll_kernel<<<dim3(768, 2), 256>>>(embW[0], embW[1], W1[0], W1[1], W2[0], W2[1]);

    // embedding, both branches in one launch
    mma_gemm<0, 0><<<dim3(GRID_M, 1, 2), 256>>>(x[0], x[1], eB, embB[0], embB[1],
                                                nullptr, nullptr, nullptr, nullptr,
                                                nullptr, nullptr);

    for (int i = 0; i < 4; i++) {
        init_agg_kernel<<<dim3(6250, 2), 256>>>(eps[0] + i, eps[1] + i);
        scatter_kernel<<<dim3(100000, 2), 256>>>(ei[0], ei[1]);
        mma_gemm<1, 0><<<dim3(GRID_M, 2, 2), 256>>>(nullptr, nullptr,
            w1B + (size_t)i * 256 * 128, b1[0] + i * 256, b1[1] + i * 256,
            nullptr, nullptr, nullptr, nullptr, nullptr, nullptr);
        if (i < 3) {
            mma_gemm<2, 0><<<dim3(GRID_M, 1, 2), 256>>>(nullptr, nullptr,
                w2B + (size_t)i * 128 * 256, b2[0] + i * 128, b2[1] + i * 128,
                gam[0] + i * 256, gam[1] + i * 256, bet[0] + i * 256, bet[1] + i * 256,
                nullptr, nullptr);
        } else {   // last layer: fused pool, no hb store, no pool kernel
            mma_gemm<2, 1><<<dim3(GRID_M, 1, 2), 256>>>(nullptr, nullptr,
                w2B + (size_t)i * 128 * 256, b2[0] + i * 128, b2[1] + i * 128,
                gam[0] + i * 256, gam[1] + i * 256, bet[0] + i * 256, bet[1] + i * 256,
                batch[0], batch[1]);
        }
    }

    head1_kernel<<<64, 256>>>((const float*)d_in[24], (const float*)d_in[25]);
    head2_kernel<<<64, 64>>>((const float*)d_in[26], (const float*)d_in[27]);
    head3_kernel<<<1, 64>>>((const float*)d_in[28], (const float*)d_in[29], (float*)d_out);
}